// round 16
// baseline (speedup 1.0000x reference)
#include <cuda_runtime.h>
#include <cuda_bf16.h>
#include <math.h>
#include <stdint.h>

#define LEAKY 0.2f

// ---------------------------------------------------------------------------
// Scratch (__device__ globals; no allocations allowed)
// ---------------------------------------------------------------------------
__device__ float g_asrc[64 * 1024];
__device__ float g_adst[64 * 1024];
__device__ uint32_t g_mask[8 * 1024 * 32];                  // adj bitmask [b][n][32]
__device__ __align__(16) __nv_bfloat16 g_Ah[8192 * 768];    // feat_in hi
__device__ __align__(16) __nv_bfloat16 g_Al[8192 * 768];    // feat_in lo
__device__ __align__(16) __nv_bfloat16 g_Wh[8 * 96 * 768];  // W^T [h][o][k] hi
__device__ __align__(16) __nv_bfloat16 g_Wl[8 * 96 * 768];
__device__ __align__(16) __nv_bfloat16 g_Hwh[768 * 768];    // Hw [o][k] hi
__device__ __align__(16) __nv_bfloat16 g_Hwl[768 * 768];
__device__ __align__(16) __nv_bfloat16 g_hTh[(size_t)64 * 96 * 1024]; // h^T [bh][o][n] hi
__device__ __align__(16) __nv_bfloat16 g_hTl[(size_t)64 * 96 * 1024]; // lo

// ---------------------------------------------------------------------------
// Helpers
// ---------------------------------------------------------------------------
__device__ __forceinline__ void mma16816(float* c, const uint32_t* a, const uint32_t* b) {
    asm volatile(
        "mma.sync.aligned.m16n8k16.row.col.f32.bf16.bf16.f32 "
        "{%0,%1,%2,%3}, {%4,%5,%6,%7}, {%8,%9}, {%0,%1,%2,%3};"
        : "+f"(c[0]), "+f"(c[1]), "+f"(c[2]), "+f"(c[3])
        : "r"(a[0]), "r"(a[1]), "r"(a[2]), "r"(a[3]), "r"(b[0]), "r"(b[1]));
}
__device__ __forceinline__ void ldsm_x4(uint32_t* r, uint32_t addr) {
    asm volatile("ldmatrix.sync.aligned.m8n8.x4.shared.b16 {%0,%1,%2,%3}, [%4];"
        : "=r"(r[0]), "=r"(r[1]), "=r"(r[2]), "=r"(r[3]) : "r"(addr));
}
__device__ __forceinline__ uint32_t pack_bf2(float a, float b) {
    __nv_bfloat162 t = __floats2bfloat162_rn(a, b);
    return *(uint32_t*)&t;
}
__device__ __forceinline__ uint32_t smem_u32(const void* p) {
    uint32_t a;
    asm("{ .reg .u64 t; cvta.to.shared.u64 t, %1; cvt.u32.u64 %0, t; }"
        : "=r"(a) : "l"(p));
    return a;
}
__device__ __forceinline__ void cp16(uint32_t dst, const void* src) {
    asm volatile("cp.async.cg.shared.global [%0], [%1], 16;" :: "r"(dst), "l"(src));
}
#define CP_COMMIT() asm volatile("cp.async.commit_group;")
#define CP_WAIT0()  asm volatile("cp.async.wait_group 0;" ::: "memory")
#define CP_WAIT1()  asm volatile("cp.async.wait_group 1;" ::: "memory")

// FMA/ALU-pipe exp (no MUFU): exp(x) = 2^n * P(r), t = x*log2e, n = rint(t),
// r = t - n in [-0.5, 0.5]. Degree-6 Taylor of 2^r, rel err ~3e-8.
// Valid for |x| <= ~80 (here logits are tanh-bounded, |x| <= ~17).
__device__ __forceinline__ float fexp(float x) {
    float t = x * 1.4426950408889634f;
    float fn = rintf(t);
    float r = t - fn;
    float p = 1.5403530393381606e-4f;
    p = fmaf(p, r, 1.3333558146428443e-3f);
    p = fmaf(p, r, 9.6181298420718032e-3f);
    p = fmaf(p, r, 5.5504108664821580e-2f);
    p = fmaf(p, r, 2.4022650695910071e-1f);
    p = fmaf(p, r, 6.9314718055994531e-1f);
    p = fmaf(p, r, 1.0f);
    int n = (int)fn;
    float s = __int_as_float((uint32_t)(n + 127) << 23);
    return s * p;
}

// Operand buffer layout (per buffer, stride 35840B):
//   AH 0 / AL 10240 : 128 rows x 80B ; WH 20480 / WL 28160 : 96 rows x 80B
#define BUF_STRIDE 35840
#define O_AH 0
#define O_AL 10240
#define O_WH 20480
#define O_WL 28160
// proj/gate: 3 buffers + vec
#define SM3_VEC 107520
#define SM3_TOT 108288
// attn: 3 operand buffers + adst + ss (adj is a register bitmask)
#define SM2_ADST 107520
#define SM2_SS   111616
#define SM2_TOT  112128

// ---------------------------------------------------------------------------
// Prep kernels
// ---------------------------------------------------------------------------
__global__ __launch_bounds__(256) void k_prep_a(
    const float* __restrict__ A, const float* __restrict__ Hw)
{
    int i = blockIdx.x * 256 + threadIdx.x;
    if (i < 8192 * 768) {
        float x = A[i];
        __nv_bfloat16 hi = __float2bfloat16(x);
        g_Ah[i] = hi;
        g_Al[i] = __float2bfloat16(x - __bfloat162float(hi));
    }
    if (i < 768 * 768) {
        float x = Hw[i];
        __nv_bfloat16 hi = __float2bfloat16(x);
        g_Hwh[i] = hi;
        g_Hwl[i] = __float2bfloat16(x - __bfloat162float(hi));
    }
}
__global__ __launch_bounds__(256) void k_prep_w(const float* __restrict__ W)
{
    int i = blockIdx.x * 256 + threadIdx.x;
    if (i < 8 * 96 * 768) {
        int k = i % 768, t = i / 768;
        int o = t % 96, hh = t / 96;
        float x = W[((size_t)hh * 768 + k) * 96 + o];
        __nv_bfloat16 hi = __float2bfloat16(x);
        g_Wh[i] = hi;
        g_Wl[i] = __float2bfloat16(x - __bfloat162float(hi));
    }
}
// adj (fp32 0/1) -> bitmask, one warp ballot per 32 elements
__global__ __launch_bounds__(256) void k_prep_mask(const float* __restrict__ adj)
{
    int gid = blockIdx.x * 256 + threadIdx.x;   // 8*1024*1024 threads
    float v = adj[gid];
    uint32_t b = __ballot_sync(0xffffffffu, v != 0.f);
    if ((threadIdx.x & 31) == 0) g_mask[gid >> 5] = b;
}

// ---------------------------------------------------------------------------
// MMA inner step (LDSM fragment loads): 2 k16 sub-steps on one buffer.
// ---------------------------------------------------------------------------
__device__ __forceinline__ void mma_chunk(
    uint32_t sbuf, float acc[2][6][4], int wm, int wn,
    uint32_t a_off, uint32_t b_off)
{
#pragma unroll
    for (int ks = 0; ks < 2; ++ks) {
        const int kb = ks * 32;
        uint32_t ahi[2][4], alo[2][4], bhi[3][4], blo[3][4];
#pragma unroll
        for (int ma = 0; ma < 2; ++ma) {
            uint32_t ab = sbuf + (wm * 32 + ma * 16) * 80 + kb + a_off;
            ldsm_x4(ahi[ma], ab + O_AH);
            ldsm_x4(alo[ma], ab + O_AL);
        }
#pragma unroll
        for (int nq = 0; nq < 3; ++nq) {
            uint32_t bb2 = sbuf + (wn * 48 + nq * 16) * 80 + kb + b_off;
            ldsm_x4(bhi[nq], bb2 + O_WH);
            ldsm_x4(blo[nq], bb2 + O_WL);
        }
#pragma unroll
        for (int na = 0; na < 6; ++na) {
            const uint32_t* bh_ = &bhi[na >> 1][(na & 1) * 2];
            const uint32_t* bl_ = &blo[na >> 1][(na & 1) * 2];
#pragma unroll
            for (int ma = 0; ma < 2; ++ma) {
                mma16816(acc[ma][na], ahi[ma], bh_);
                mma16816(acc[ma][na], ahi[ma], bl_);
                mma16816(acc[ma][na], alo[ma], bh_);
            }
        }
    }
}
// Lane-constant ldmatrix offsets
__device__ __forceinline__ uint32_t mk_a_off(int lane) {
    int m = lane >> 3, rl = lane & 7;
    return (uint32_t)((rl + (m & 1) * 8) * 80 + (m >> 1) * 16);
}
__device__ __forceinline__ uint32_t mk_b_off(int lane) {
    int m = lane >> 3, rl = lane & 7;
    return (uint32_t)((rl + (m >> 1) * 8) * 80 + (m & 1) * 16);
}

// ---------------------------------------------------------------------------
// Kernel 1 (HMMA, 3-deep cp.async pipeline): h = feat_in @ W[h].
// ---------------------------------------------------------------------------
__global__ void __launch_bounds__(256, 2) k_proj_mma(
    const float* __restrict__ wsrc, const float* __restrict__ wdst)
{
    extern __shared__ __align__(16) char ds[];
    const uint32_t sb = smem_u32(ds);
    const int tid  = threadIdx.x;
    const int wid  = tid >> 5, lane = tid & 31;
    const int g    = lane >> 2, tig = lane & 3;
    const int wm   = wid & 3, wn = wid >> 2;
    const int row0 = blockIdx.x * 128, h = blockIdx.y;
    const int ar   = tid >> 2, ac = tid & 3;
    const uint32_t a_off = mk_a_off(lane), b_off = mk_b_off(lane);

    float* wsv = (float*)(ds + SM3_VEC);
    if (tid < 96) {
        wsv[tid]      = wsrc[h * 96 + tid];
        wsv[96 + tid] = wdst[h * 96 + tid];
    }

    float acc[2][6][4];
#pragma unroll
    for (int ma = 0; ma < 2; ++ma)
#pragma unroll
        for (int na = 0; na < 6; ++na)
#pragma unroll
            for (int q = 0; q < 4; ++q) acc[ma][na][q] = 0.f;

    const uint4* __restrict__ Ah4 = (const uint4*)g_Ah;
    const uint4* __restrict__ Al4 = (const uint4*)g_Al;
    const uint4* __restrict__ Wh4 = (const uint4*)g_Wh;
    const uint4* __restrict__ Wl4 = (const uint4*)g_Wl;

    auto fill = [&](uint32_t bb, int k4) {
#pragma unroll
        for (int it = 0; it < 2; ++it) {
            int r = ar + it * 64;
            cp16(bb + O_AH + r * 80 + ac * 16, &Ah4[(row0 + r) * 96 + k4 + ac]);
            cp16(bb + O_AL + r * 80 + ac * 16, &Al4[(row0 + r) * 96 + k4 + ac]);
        }
        cp16(bb + O_WH + ar * 80 + ac * 16, &Wh4[(h * 96 + ar) * 96 + k4 + ac]);
        cp16(bb + O_WL + ar * 80 + ac * 16, &Wl4[(h * 96 + ar) * 96 + k4 + ac]);
        if (tid < 128) {
            cp16(bb + O_WH + (ar + 64) * 80 + ac * 16, &Wh4[(h * 96 + ar + 64) * 96 + k4 + ac]);
            cp16(bb + O_WL + (ar + 64) * 80 + ac * 16, &Wl4[(h * 96 + ar + 64) * 96 + k4 + ac]);
        }
        CP_COMMIT();
    };

    fill(sb, 0);
    fill(sb + BUF_STRIDE, 4);

    for (int ch = 0; ch < 24; ++ch) {
        if (ch < 22) CP_WAIT1(); else CP_WAIT0();
        __syncthreads();
        if (ch < 22) fill(sb + ((ch + 2) % 3) * BUF_STRIDE, (ch + 2) * 4);
        mma_chunk(sb + (ch % 3) * BUF_STRIDE, acc, wm, wn, a_off, b_off);
    }
    __syncthreads();

    float* dtile = (float*)ds;   // [128][97] overlays buffers
#pragma unroll
    for (int ma = 0; ma < 2; ++ma)
#pragma unroll
        for (int na = 0; na < 6; ++na) {
            int rb = wm * 32 + ma * 16 + g;
            int cb = wn * 48 + na * 8 + 2 * tig;
            dtile[rb * 97 + cb]           = acc[ma][na][0];
            dtile[rb * 97 + cb + 1]       = acc[ma][na][1];
            dtile[(rb + 8) * 97 + cb]     = acc[ma][na][2];
            dtile[(rb + 8) * 97 + cb + 1] = acc[ma][na][3];
        }
    __syncthreads();

    const int batch = row0 >> 10, bh = batch * 8 + h;
    const int nbase = row0 & 1023;
    {   // a_src/a_dst: 2 threads per row
        int r = tid >> 1, half = tid & 1;
        float ps = 0.f, pd = 0.f;
#pragma unroll
        for (int cc = 0; cc < 48; ++cc) {
            int c = half * 48 + cc;
            float t = tanhf(dtile[r * 97 + c]);
            ps = fmaf(t, wsv[c], ps);
            pd = fmaf(t, wsv[96 + c], pd);
        }
        ps += __shfl_xor_sync(0xffffffffu, ps, 1);
        pd += __shfl_xor_sync(0xffffffffu, pd, 1);
        if (half == 0) {
            g_asrc[(size_t)bh * 1024 + nbase + r] = ps;
            g_adst[(size_t)bh * 1024 + nbase + r] = pd;
        }
    }
    // h^T bf16 split, coalesced along n
    for (int idx = tid; idx < 96 * 64; idx += 256) {
        int o = idx >> 6, nw = idx & 63;
        float v0 = dtile[(2 * nw) * 97 + o];
        float v1 = dtile[(2 * nw + 1) * 97 + o];
        __nv_bfloat16 b0 = __float2bfloat16(v0);
        __nv_bfloat16 b1 = __float2bfloat16(v1);
        uint32_t hi = pack_bf2(v0, v1);
        uint32_t lo = pack_bf2(v0 - __bfloat162float(b0), v1 - __bfloat162float(b1));
        size_t dst = ((size_t)bh * 96 + o) * 512 + (nbase >> 1) + nw;
        ((uint32_t*)g_hTh)[dst] = hi;
        ((uint32_t*)g_hTl)[dst] = lo;
    }
}

// ---------------------------------------------------------------------------
// p-tile compute: bitmask gate, unnormalized exp (FMA-pipe fexp, no MUFU),
// bf16 hi/lo split, streamed to target buffer.
// ---------------------------------------------------------------------------
__device__ __forceinline__ void compute_p(
    uint32_t mw, const float* adst_s, float asr,
    int j0, int pi, int phalf, float& ssum, uint32_t bb)
{
    const int off = pi * 80 + phalf * 32;
#pragma unroll
    for (int q = 0; q < 4; ++q) {
        int jj = phalf * 16 + q * 4;
        float pv[4];
#pragma unroll
        for (int t = 0; t < 4; ++t) {
            float l = asr + adst_s[j0 + jj + t];
            l = l >= 0.f ? l : LEAKY * l;
            float e = fexp(l);
            float p = ((mw >> (jj + t)) & 1u) ? e : 0.f;
            ssum += p;
            pv[t] = p;
        }
        __nv_bfloat16 b0 = __float2bfloat16(pv[0]);
        __nv_bfloat16 b1 = __float2bfloat16(pv[1]);
        __nv_bfloat16 b2 = __float2bfloat16(pv[2]);
        __nv_bfloat16 b3 = __float2bfloat16(pv[3]);
        uint32_t h0 = pack_bf2(pv[0], pv[1]);
        uint32_t h1 = pack_bf2(pv[2], pv[3]);
        uint32_t l0 = pack_bf2(pv[0] - __bfloat162float(b0), pv[1] - __bfloat162float(b1));
        uint32_t l1 = pack_bf2(pv[2] - __bfloat162float(b2), pv[3] - __bfloat162float(b3));
        asm volatile("st.shared.v2.b32 [%0], {%1, %2};"
                     :: "r"(bb + O_AH + off + q * 8), "r"(h0), "r"(h1) : "memory");
        asm volatile("st.shared.v2.b32 [%0], {%1, %2};"
                     :: "r"(bb + O_AL + off + q * 8), "r"(l0), "r"(l1) : "memory");
    }
}

// ---------------------------------------------------------------------------
// Kernel 2 (HMMA, 3-deep h pipeline + bitmask adj): masked softmax attention.
// ---------------------------------------------------------------------------
__global__ void __launch_bounds__(256, 2) k_attn_mma(
    const float* __restrict__ bias,  // [96]
    float* __restrict__ out)         // [B,1024,768]
{
    extern __shared__ __align__(16) char ds[];
    const uint32_t sb = smem_u32(ds);
    const int tid = threadIdx.x;
    const int wid = tid >> 5, lane = tid & 31;
    const int g   = lane >> 2, tig = lane & 3;
    const int wm  = wid & 3, wn = wid >> 2;
    const int bh  = blockIdx.x, batch = bh >> 3, h = bh & 7;
    const int i0  = blockIdx.y * 128;
    const int hr  = tid >> 2, hc = tid & 3;
    const uint32_t a_off = mk_a_off(lane), b_off = mk_b_off(lane);

    float* adst_s = (float*)(ds + SM2_ADST);
    for (int j = tid; j < 1024; j += 256)
        adst_s[j] = g_adst[(size_t)bh * 1024 + j];

    const int pi = tid >> 1, phalf = tid & 1;
    const float asr = g_asrc[(size_t)bh * 1024 + i0 + pi];
    const uint32_t* mrow = &g_mask[(size_t)(batch * 1024 + i0 + pi) * 32];
    float ssum = 0.f;

    float acc[2][6][4];
#pragma unroll
    for (int ma = 0; ma < 2; ++ma)
#pragma unroll
        for (int na = 0; na < 6; ++na)
#pragma unroll
            for (int q = 0; q < 4; ++q) acc[ma][na][q] = 0.f;

    const uint4* __restrict__ Hh4 = (const uint4*)g_hTh;
    const uint4* __restrict__ Hl4 = (const uint4*)g_hTl;

    auto fill_h = [&](uint32_t bb, int j8) {
        cp16(bb + O_WH + hr * 80 + hc * 16, &Hh4[(bh * 96 + hr) * 128 + j8 + hc]);
        cp16(bb + O_WL + hr * 80 + hc * 16, &Hl4[(bh * 96 + hr) * 128 + j8 + hc]);
        if (tid < 128) {
            cp16(bb + O_WH + (hr + 64) * 80 + hc * 16, &Hh4[(bh * 96 + hr + 64) * 128 + j8 + hc]);
            cp16(bb + O_WL + (hr + 64) * 80 + hc * 16, &Hl4[(bh * 96 + hr + 64) * 128 + j8 + hc]);
        }
        CP_COMMIT();
    };

    // prologue: h[0], h[1] in flight; p[0] after adst is published
    fill_h(sb, 0);
    fill_h(sb + BUF_STRIDE, 4);
    __syncthreads();                 // adst_s visible
    compute_p(__ldg(&mrow[0]), adst_s, asr, 0, pi, phalf, ssum, sb);

    for (int cc = 0; cc < 32; ++cc) {
        if (cc < 31) CP_WAIT1(); else CP_WAIT0();
        __syncthreads();   // publishes h[cc] + p[cc]; prev MMA reads complete
        if (cc < 30) fill_h(sb + ((cc + 2) % 3) * BUF_STRIDE, (cc + 2) * 4);
        if (cc < 31)
            compute_p(__ldg(&mrow[cc + 1]), adst_s, asr, (cc + 1) * 32,
                      pi, phalf, ssum, sb + ((cc + 1) % 3) * BUF_STRIDE);
        mma_chunk(sb + (cc % 3) * BUF_STRIDE, acc, wm, wn, a_off, b_off);
    }

    // row sums
    ssum += __shfl_xor_sync(0xffffffffu, ssum, 1);
    float* ss = (float*)(ds + SM2_SS);
    if (phalf == 0) ss[pi] = ssum;
    __syncthreads();

    float* dtile = (float*)ds;
#pragma unroll
    for (int ma = 0; ma < 2; ++ma)
#pragma unroll
        for (int na = 0; na < 6; ++na) {
            int rb = wm * 32 + ma * 16 + g;
            int cb = wn * 48 + na * 8 + 2 * tig;
            dtile[rb * 97 + cb]           = acc[ma][na][0];
            dtile[rb * 97 + cb + 1]       = acc[ma][na][1];
            dtile[(rb + 8) * 97 + cb]     = acc[ma][na][2];
            dtile[(rb + 8) * 97 + cb + 1] = acc[ma][na][3];
        }
    __syncthreads();

    for (int i = tid; i < 128 * 96; i += 256) {
        int r = i / 96, c = i - r * 96;
        float v = dtile[r * 97 + c] * (1.f / ss[r]) + __ldg(&bias[c]);
        v = v > 0.f ? v : expm1f(v);
        out[((size_t)batch * 1024 + i0 + r) * 768 + h * 96 + c] = v;
    }
}

// ---------------------------------------------------------------------------
// Kernel 3 (HMMA, 3-deep cp.async pipeline): gate GEMM + sigmoid + blend.
// ---------------------------------------------------------------------------
__global__ void __launch_bounds__(256, 2) k_gate_mma(
    const float* __restrict__ X, const float* __restrict__ Hb,
    float* __restrict__ out)
{
    extern __shared__ __align__(16) char ds[];
    const uint32_t sb = smem_u32(ds);
    const int tid  = threadIdx.x;
    const int wid  = tid >> 5, lane = tid & 31;
    const int g    = lane >> 2, tig = lane & 3;
    const int wm   = wid & 3, wn = wid >> 2;
    const int row0 = blockIdx.x * 128, c0 = blockIdx.y * 96;
    const int ar   = tid >> 2, ac = tid & 3;
    const uint32_t a_off = mk_a_off(lane), b_off = mk_b_off(lane);

    float* hbv = (float*)(ds + SM3_VEC);
    if (tid < 96) hbv[tid] = Hb[c0 + tid];

    float acc[2][6][4];
#pragma unroll
    for (int ma = 0; ma < 2; ++ma)
#pragma unroll
        for (int na = 0; na < 6; ++na)
#pragma unroll
            for (int q = 0; q < 4; ++q) acc[ma][na][q] = 0.f;

    const uint4* __restrict__ Ah4 = (const uint4*)g_Ah;
    const uint4* __restrict__ Al4 = (const uint4*)g_Al;
    const uint4* __restrict__ Wh4 = (const uint4*)g_Hwh;
    const uint4* __restrict__ Wl4 = (const uint4*)g_Hwl;

    auto fill = [&](uint32_t bb, int k4) {
#pragma unroll
        for (int it = 0; it < 2; ++it) {
            int r = ar + it * 64;
            cp16(bb + O_AH + r * 80 + ac * 16, &Ah4[(row0 + r) * 96 + k4 + ac]);
            cp16(bb + O_AL + r * 80 + ac * 16, &Al4[(row0 + r) * 96 + k4 + ac]);
        }
        cp16(bb + O_WH + ar * 80 + ac * 16, &Wh4[(c0 + ar) * 96 + k4 + ac]);
        cp16(bb + O_WL + ar * 80 + ac * 16, &Wl4[(c0 + ar) * 96 + k4 + ac]);
        if (tid < 128) {
            cp16(bb + O_WH + (ar + 64) * 80 + ac * 16, &Wh4[(c0 + ar + 64) * 96 + k4 + ac]);
            cp16(bb + O_WL + (ar + 64) * 80 + ac * 16, &Wl4[(c0 + ar + 64) * 96 + k4 + ac]);
        }
        CP_COMMIT();
    };

    fill(sb, 0);
    fill(sb + BUF_STRIDE, 4);

    for (int ch = 0; ch < 24; ++ch) {
        if (ch < 22) CP_WAIT1(); else CP_WAIT0();
        __syncthreads();
        if (ch < 22) fill(sb + ((ch + 2) % 3) * BUF_STRIDE, (ch + 2) * 4);
        mma_chunk(sb + (ch % 3) * BUF_STRIDE, acc, wm, wn, a_off, b_off);
    }
    __syncthreads();

    float* dtile = (float*)ds;
#pragma unroll
    for (int ma = 0; ma < 2; ++ma)
#pragma unroll
        for (int na = 0; na < 6; ++na) {
            int rb = wm * 32 + ma * 16 + g;
            int cb = wn * 48 + na * 8 + 2 * tig;
            dtile[rb * 97 + cb]           = acc[ma][na][0];
            dtile[rb * 97 + cb + 1]       = acc[ma][na][1];
            dtile[(rb + 8) * 97 + cb]     = acc[ma][na][2];
            dtile[(rb + 8) * 97 + cb + 1] = acc[ma][na][3];
        }
    __syncthreads();

    for (int i = tid; i < 128 * 96; i += 256) {
        int r = i / 96, c = i - r * 96;
        int row = row0 + r, col = c0 + c;
        float v = dtile[r * 97 + c];
        float gg = 1.f / (1.f + fexp(-(v + hbv[c])));
        size_t idx = (size_t)row * 768 + col;
        float fo = out[idx], xi = X[idx];
        out[idx] = fmaf(gg, fo - xi, xi);
    }
}

// ---------------------------------------------------------------------------
// Inputs (metadata order): feat_in, adj, W, b, w_src, w_dst, Hw, Hb
// ---------------------------------------------------------------------------
extern "C" void kernel_launch(void* const* d_in, const int* in_sizes, int n_in,
                              void* d_out, int out_size)
{
    const float* feat_in = (const float*)d_in[0];
    const float* adj     = (const float*)d_in[1];
    const float* W       = (const float*)d_in[2];
    const float* bias    = (const float*)d_in[3];
    const float* wsrc    = (const float*)d_in[4];
    const float* wdst    = (const float*)d_in[5];
    const float* Hw      = (const float*)d_in[6];
    const float* Hb      = (const float*)d_in[7];
    float* out           = (float*)d_out;
    (void)in_sizes; (void)n_in; (void)out_size;

    static bool attr_done = false;
    if (!attr_done) {
        cudaFuncSetAttribute(k_proj_mma, cudaFuncAttributeMaxDynamicSharedMemorySize, SM3_TOT);
        cudaFuncSetAttribute(k_attn_mma, cudaFuncAttributeMaxDynamicSharedMemorySize, SM2_TOT);
        cudaFuncSetAttribute(k_gate_mma, cudaFuncAttributeMaxDynamicSharedMemorySize, SM3_TOT);
        attr_done = true;
    }

    k_prep_a<<<(8192 * 768 + 255) / 256, 256>>>(feat_in, Hw);
    k_prep_w<<<(8 * 96 * 768 + 255) / 256, 256>>>(W);
    k_prep_mask<<<(8 * 1024 * 1024) / 256, 256>>>(adj);
    k_proj_mma<<<dim3(64, 8), 256, SM3_TOT>>>(wsrc, wdst);
    k_attn_mma<<<dim3(64, 8), 256, SM2_TOT>>>(bias, out);
    k_gate_mma<<<dim3(64, 8), 256, SM3_TOT>>>(feat_in, Hb, out);
}

// round 17
// speedup vs baseline: 1.0874x; 1.0874x over previous
#include <cuda_runtime.h>
#include <cuda_bf16.h>
#include <math.h>
#include <stdint.h>

#define LEAKY 0.2f

// ---------------------------------------------------------------------------
// Scratch (__device__ globals; no allocations allowed)
// ---------------------------------------------------------------------------
__device__ float g_asrc[64 * 1024];
__device__ float g_adst[64 * 1024];
__device__ uint32_t g_mask[8 * 1024 * 32];                  // adj bitmask [b][n][32]
__device__ __align__(16) __nv_bfloat16 g_Ah[8192 * 768];    // feat_in hi
__device__ __align__(16) __nv_bfloat16 g_Al[8192 * 768];    // feat_in lo
__device__ __align__(16) __nv_bfloat16 g_Wh[8 * 96 * 768];  // W^T [h][o][k] hi
__device__ __align__(16) __nv_bfloat16 g_Wl[8 * 96 * 768];
__device__ __align__(16) __nv_bfloat16 g_Hwh[768 * 768];    // Hw [o][k] hi
__device__ __align__(16) __nv_bfloat16 g_Hwl[768 * 768];
__device__ __align__(16) __nv_bfloat16 g_hTh[(size_t)64 * 96 * 1024]; // h^T [bh][o][n] hi
__device__ __align__(16) __nv_bfloat16 g_hTl[(size_t)64 * 96 * 1024]; // lo

// ---------------------------------------------------------------------------
// Helpers
// ---------------------------------------------------------------------------
__device__ __forceinline__ void mma16816(float* c, const uint32_t* a, const uint32_t* b) {
    asm volatile(
        "mma.sync.aligned.m16n8k16.row.col.f32.bf16.bf16.f32 "
        "{%0,%1,%2,%3}, {%4,%5,%6,%7}, {%8,%9}, {%0,%1,%2,%3};"
        : "+f"(c[0]), "+f"(c[1]), "+f"(c[2]), "+f"(c[3])
        : "r"(a[0]), "r"(a[1]), "r"(a[2]), "r"(a[3]), "r"(b[0]), "r"(b[1]));
}
__device__ __forceinline__ void ldsm_x4(uint32_t* r, uint32_t addr) {
    asm volatile("ldmatrix.sync.aligned.m8n8.x4.shared.b16 {%0,%1,%2,%3}, [%4];"
        : "=r"(r[0]), "=r"(r[1]), "=r"(r[2]), "=r"(r[3]) : "r"(addr));
}
__device__ __forceinline__ uint32_t pack_bf2(float a, float b) {
    __nv_bfloat162 t = __floats2bfloat162_rn(a, b);
    return *(uint32_t*)&t;
}
__device__ __forceinline__ uint32_t smem_u32(const void* p) {
    uint32_t a;
    asm("{ .reg .u64 t; cvta.to.shared.u64 t, %1; cvt.u32.u64 %0, t; }"
        : "=r"(a) : "l"(p));
    return a;
}
__device__ __forceinline__ void cp16(uint32_t dst, const void* src) {
    asm volatile("cp.async.cg.shared.global [%0], [%1], 16;" :: "r"(dst), "l"(src));
}
#define CP_COMMIT() asm volatile("cp.async.commit_group;")
#define CP_WAIT0()  asm volatile("cp.async.wait_group 0;" ::: "memory")
#define CP_WAIT1()  asm volatile("cp.async.wait_group 1;" ::: "memory")

// Operand buffer layout (per buffer, stride 35840B):
//   AH 0 / AL 10240 : 128 rows x 80B ; WH 20480 / WL 28160 : 96 rows x 80B
#define BUF_STRIDE 35840
#define O_AH 0
#define O_AL 10240
#define O_WH 20480
#define O_WL 28160
// proj: 3 buffers + vec
#define SM3_VEC 107520
#define SM3_TOT 108288
// fused attn+gate: 3 operand buffers + adst + ss
#define SM2_ADST 107520
#define SM2_SS   111616
#define SM2_TOT  112128

// ---------------------------------------------------------------------------
// Prep kernels
// ---------------------------------------------------------------------------
__global__ __launch_bounds__(256) void k_prep_a(
    const float* __restrict__ A, const float* __restrict__ Hw)
{
    int i = blockIdx.x * 256 + threadIdx.x;
    if (i < 8192 * 768) {
        float x = A[i];
        __nv_bfloat16 hi = __float2bfloat16(x);
        g_Ah[i] = hi;
        g_Al[i] = __float2bfloat16(x - __bfloat162float(hi));
    }
    if (i < 768 * 768) {
        float x = Hw[i];
        __nv_bfloat16 hi = __float2bfloat16(x);
        g_Hwh[i] = hi;
        g_Hwl[i] = __float2bfloat16(x - __bfloat162float(hi));
    }
}
__global__ __launch_bounds__(256) void k_prep_w(const float* __restrict__ W)
{
    int i = blockIdx.x * 256 + threadIdx.x;
    if (i < 8 * 96 * 768) {
        int k = i % 768, t = i / 768;
        int o = t % 96, hh = t / 96;
        float x = W[((size_t)hh * 768 + k) * 96 + o];
        __nv_bfloat16 hi = __float2bfloat16(x);
        g_Wh[i] = hi;
        g_Wl[i] = __float2bfloat16(x - __bfloat162float(hi));
    }
}
// adj (fp32 0/1) -> bitmask, one warp ballot per 32 elements
__global__ __launch_bounds__(256) void k_prep_mask(const float* __restrict__ adj)
{
    int gid = blockIdx.x * 256 + threadIdx.x;   // 8*1024*1024 threads
    float v = adj[gid];
    uint32_t b = __ballot_sync(0xffffffffu, v != 0.f);
    if ((threadIdx.x & 31) == 0) g_mask[gid >> 5] = b;
}

// ---------------------------------------------------------------------------
// MMA inner step (LDSM fragment loads): 2 k16 sub-steps on one buffer.
// ---------------------------------------------------------------------------
__device__ __forceinline__ void mma_chunk(
    uint32_t sbuf, float acc[2][6][4], int wm, int wn,
    uint32_t a_off, uint32_t b_off)
{
#pragma unroll
    for (int ks = 0; ks < 2; ++ks) {
        const int kb = ks * 32;
        uint32_t ahi[2][4], alo[2][4], bhi[3][4], blo[3][4];
#pragma unroll
        for (int ma = 0; ma < 2; ++ma) {
            uint32_t ab = sbuf + (wm * 32 + ma * 16) * 80 + kb + a_off;
            ldsm_x4(ahi[ma], ab + O_AH);
            ldsm_x4(alo[ma], ab + O_AL);
        }
#pragma unroll
        for (int nq = 0; nq < 3; ++nq) {
            uint32_t bb2 = sbuf + (wn * 48 + nq * 16) * 80 + kb + b_off;
            ldsm_x4(bhi[nq], bb2 + O_WH);
            ldsm_x4(blo[nq], bb2 + O_WL);
        }
#pragma unroll
        for (int na = 0; na < 6; ++na) {
            const uint32_t* bh_ = &bhi[na >> 1][(na & 1) * 2];
            const uint32_t* bl_ = &blo[na >> 1][(na & 1) * 2];
#pragma unroll
            for (int ma = 0; ma < 2; ++ma) {
                mma16816(acc[ma][na], ahi[ma], bh_);
                mma16816(acc[ma][na], ahi[ma], bl_);
                mma16816(acc[ma][na], alo[ma], bh_);
            }
        }
    }
}
// Lane-constant ldmatrix offsets
__device__ __forceinline__ uint32_t mk_a_off(int lane) {
    int m = lane >> 3, rl = lane & 7;
    return (uint32_t)((rl + (m & 1) * 8) * 80 + (m >> 1) * 16);
}
__device__ __forceinline__ uint32_t mk_b_off(int lane) {
    int m = lane >> 3, rl = lane & 7;
    return (uint32_t)((rl + (m >> 1) * 8) * 80 + (m & 1) * 16);
}

// ---------------------------------------------------------------------------
// Kernel 1 (HMMA, 3-deep cp.async pipeline): h = feat_in @ W[h].
// ---------------------------------------------------------------------------
__global__ void __launch_bounds__(256, 2) k_proj_mma(
    const float* __restrict__ wsrc, const float* __restrict__ wdst)
{
    extern __shared__ __align__(16) char ds[];
    const uint32_t sb = smem_u32(ds);
    const int tid  = threadIdx.x;
    const int wid  = tid >> 5, lane = tid & 31;
    const int g    = lane >> 2, tig = lane & 3;
    const int wm   = wid & 3, wn = wid >> 2;
    const int row0 = blockIdx.x * 128, h = blockIdx.y;
    const int ar   = tid >> 2, ac = tid & 3;
    const uint32_t a_off = mk_a_off(lane), b_off = mk_b_off(lane);

    float* wsv = (float*)(ds + SM3_VEC);
    if (tid < 96) {
        wsv[tid]      = wsrc[h * 96 + tid];
        wsv[96 + tid] = wdst[h * 96 + tid];
    }

    float acc[2][6][4];
#pragma unroll
    for (int ma = 0; ma < 2; ++ma)
#pragma unroll
        for (int na = 0; na < 6; ++na)
#pragma unroll
            for (int q = 0; q < 4; ++q) acc[ma][na][q] = 0.f;

    const uint4* __restrict__ Ah4 = (const uint4*)g_Ah;
    const uint4* __restrict__ Al4 = (const uint4*)g_Al;
    const uint4* __restrict__ Wh4 = (const uint4*)g_Wh;
    const uint4* __restrict__ Wl4 = (const uint4*)g_Wl;

    auto fill = [&](uint32_t bb, int k4) {
#pragma unroll
        for (int it = 0; it < 2; ++it) {
            int r = ar + it * 64;
            cp16(bb + O_AH + r * 80 + ac * 16, &Ah4[(row0 + r) * 96 + k4 + ac]);
            cp16(bb + O_AL + r * 80 + ac * 16, &Al4[(row0 + r) * 96 + k4 + ac]);
        }
        cp16(bb + O_WH + ar * 80 + ac * 16, &Wh4[(h * 96 + ar) * 96 + k4 + ac]);
        cp16(bb + O_WL + ar * 80 + ac * 16, &Wl4[(h * 96 + ar) * 96 + k4 + ac]);
        if (tid < 128) {
            cp16(bb + O_WH + (ar + 64) * 80 + ac * 16, &Wh4[(h * 96 + ar + 64) * 96 + k4 + ac]);
            cp16(bb + O_WL + (ar + 64) * 80 + ac * 16, &Wl4[(h * 96 + ar + 64) * 96 + k4 + ac]);
        }
        CP_COMMIT();
    };

    fill(sb, 0);
    fill(sb + BUF_STRIDE, 4);

    for (int ch = 0; ch < 24; ++ch) {
        if (ch < 22) CP_WAIT1(); else CP_WAIT0();
        __syncthreads();
        if (ch < 22) fill(sb + ((ch + 2) % 3) * BUF_STRIDE, (ch + 2) * 4);
        mma_chunk(sb + (ch % 3) * BUF_STRIDE, acc, wm, wn, a_off, b_off);
    }
    __syncthreads();

    float* dtile = (float*)ds;   // [128][97] overlays buffers
#pragma unroll
    for (int ma = 0; ma < 2; ++ma)
#pragma unroll
        for (int na = 0; na < 6; ++na) {
            int rb = wm * 32 + ma * 16 + g;
            int cb = wn * 48 + na * 8 + 2 * tig;
            dtile[rb * 97 + cb]           = acc[ma][na][0];
            dtile[rb * 97 + cb + 1]       = acc[ma][na][1];
            dtile[(rb + 8) * 97 + cb]     = acc[ma][na][2];
            dtile[(rb + 8) * 97 + cb + 1] = acc[ma][na][3];
        }
    __syncthreads();

    const int batch = row0 >> 10, bh = batch * 8 + h;
    const int nbase = row0 & 1023;
    {   // a_src/a_dst: 2 threads per row
        int r = tid >> 1, half = tid & 1;
        float ps = 0.f, pd = 0.f;
#pragma unroll
        for (int cc = 0; cc < 48; ++cc) {
            int c = half * 48 + cc;
            float t = tanhf(dtile[r * 97 + c]);
            ps = fmaf(t, wsv[c], ps);
            pd = fmaf(t, wsv[96 + c], pd);
        }
        ps += __shfl_xor_sync(0xffffffffu, ps, 1);
        pd += __shfl_xor_sync(0xffffffffu, pd, 1);
        if (half == 0) {
            g_asrc[(size_t)bh * 1024 + nbase + r] = ps;
            g_adst[(size_t)bh * 1024 + nbase + r] = pd;
        }
    }
    // h^T bf16 split, coalesced along n
    for (int idx = tid; idx < 96 * 64; idx += 256) {
        int o = idx >> 6, nw = idx & 63;
        float v0 = dtile[(2 * nw) * 97 + o];
        float v1 = dtile[(2 * nw + 1) * 97 + o];
        __nv_bfloat16 b0 = __float2bfloat16(v0);
        __nv_bfloat16 b1 = __float2bfloat16(v1);
        uint32_t hi = pack_bf2(v0, v1);
        uint32_t lo = pack_bf2(v0 - __bfloat162float(b0), v1 - __bfloat162float(b1));
        size_t dst = ((size_t)bh * 96 + o) * 512 + (nbase >> 1) + nw;
        ((uint32_t*)g_hTh)[dst] = hi;
        ((uint32_t*)g_hTl)[dst] = lo;
    }
}

// ---------------------------------------------------------------------------
// p-tile compute: bitmask gate (identical math to exp(-999)=0), unnormalized
// exp of tanh-bounded logits, bf16 hi/lo split, streamed to target buffer.
// ---------------------------------------------------------------------------
__device__ __forceinline__ void compute_p(
    uint32_t mw, const float* adst_s, float asr,
    int j0, int pi, int phalf, float& ssum, uint32_t bb)
{
    const int off = pi * 80 + phalf * 32;
#pragma unroll
    for (int q = 0; q < 4; ++q) {
        int jj = phalf * 16 + q * 4;
        float pv[4];
#pragma unroll
        for (int t = 0; t < 4; ++t) {
            float l = asr + adst_s[j0 + jj + t];
            l = l >= 0.f ? l : LEAKY * l;
            float e = __expf(l);
            float p = ((mw >> (jj + t)) & 1u) ? e : 0.f;
            ssum += p;
            pv[t] = p;
        }
        __nv_bfloat16 b0 = __float2bfloat16(pv[0]);
        __nv_bfloat16 b1 = __float2bfloat16(pv[1]);
        __nv_bfloat16 b2 = __float2bfloat16(pv[2]);
        __nv_bfloat16 b3 = __float2bfloat16(pv[3]);
        uint32_t h0 = pack_bf2(pv[0], pv[1]);
        uint32_t h1 = pack_bf2(pv[2], pv[3]);
        uint32_t l0 = pack_bf2(pv[0] - __bfloat162float(b0), pv[1] - __bfloat162float(b1));
        uint32_t l1 = pack_bf2(pv[2] - __bfloat162float(b2), pv[3] - __bfloat162float(b3));
        asm volatile("st.shared.v2.b32 [%0], {%1, %2};"
                     :: "r"(bb + O_AH + off + q * 8), "r"(h0), "r"(h1) : "memory");
        asm volatile("st.shared.v2.b32 [%0], {%1, %2};"
                     :: "r"(bb + O_AL + off + q * 8), "r"(l0), "r"(l1) : "memory");
    }
}

// ---------------------------------------------------------------------------
// Kernel 2 (FUSED attn + gate): masked softmax attention (3-deep h pipeline,
// bitmask adj), fo=elu(...) written to out, then the gate GEMM for the SAME
// 128x96 tile (cols = h*96..h*96+95) and the sigmoid blend, in one kernel.
// ---------------------------------------------------------------------------
__global__ void __launch_bounds__(256, 2) k_attn_gate(
    const float* __restrict__ X,     // feat_in [8192, 768]
    const float* __restrict__ bias,  // [96]
    const float* __restrict__ Hb,    // [768]
    float* __restrict__ out)         // [B,1024,768]
{
    extern __shared__ __align__(16) char ds[];
    const uint32_t sb = smem_u32(ds);
    const int tid = threadIdx.x;
    const int wid = tid >> 5, lane = tid & 31;
    const int g   = lane >> 2, tig = lane & 3;
    const int wm  = wid & 3, wn = wid >> 2;
    const int bh  = blockIdx.x, batch = bh >> 3, h = bh & 7;
    const int i0  = blockIdx.y * 128;
    const int hr  = tid >> 2, hc = tid & 3;
    const uint32_t a_off = mk_a_off(lane), b_off = mk_b_off(lane);
    const int grow0 = batch * 1024 + i0;     // global row base
    const int c0g   = h * 96;                // gate column base

    float* adst_s = (float*)(ds + SM2_ADST);
    for (int j = tid; j < 1024; j += 256)
        adst_s[j] = g_adst[(size_t)bh * 1024 + j];

    const int pi = tid >> 1, phalf = tid & 1;
    const float asr = g_asrc[(size_t)bh * 1024 + i0 + pi];
    const uint32_t* mrow = &g_mask[(size_t)(batch * 1024 + i0 + pi) * 32];
    float ssum = 0.f;

    float acc[2][6][4];
#pragma unroll
    for (int ma = 0; ma < 2; ++ma)
#pragma unroll
        for (int na = 0; na < 6; ++na)
#pragma unroll
            for (int q = 0; q < 4; ++q) acc[ma][na][q] = 0.f;

    const uint4* __restrict__ Hh4 = (const uint4*)g_hTh;
    const uint4* __restrict__ Hl4 = (const uint4*)g_hTl;

    auto fill_h = [&](uint32_t bb, int j8) {
        cp16(bb + O_WH + hr * 80 + hc * 16, &Hh4[(bh * 96 + hr) * 128 + j8 + hc]);
        cp16(bb + O_WL + hr * 80 + hc * 16, &Hl4[(bh * 96 + hr) * 128 + j8 + hc]);
        if (tid < 128) {
            cp16(bb + O_WH + (hr + 64) * 80 + hc * 16, &Hh4[(bh * 96 + hr + 64) * 128 + j8 + hc]);
            cp16(bb + O_WL + (hr + 64) * 80 + hc * 16, &Hl4[(bh * 96 + hr + 64) * 128 + j8 + hc]);
        }
        CP_COMMIT();
    };

    // ---- Phase A: attention mainloop ----
    fill_h(sb, 0);
    fill_h(sb + BUF_STRIDE, 4);
    __syncthreads();                 // adst_s visible
    compute_p(__ldg(&mrow[0]), adst_s, asr, 0, pi, phalf, ssum, sb);

    for (int cc = 0; cc < 32; ++cc) {
        if (cc < 31) CP_WAIT1(); else CP_WAIT0();
        __syncthreads();   // publishes h[cc] + p[cc]; prev MMA reads complete
        if (cc < 30) fill_h(sb + ((cc + 2) % 3) * BUF_STRIDE, (cc + 2) * 4);
        if (cc < 31)
            compute_p(__ldg(&mrow[cc + 1]), adst_s, asr, (cc + 1) * 32,
                      pi, phalf, ssum, sb + ((cc + 1) % 3) * BUF_STRIDE);
        mma_chunk(sb + (cc % 3) * BUF_STRIDE, acc, wm, wn, a_off, b_off);
    }

    // row sums
    ssum += __shfl_xor_sync(0xffffffffu, ssum, 1);
    float* ss = (float*)(ds + SM2_SS);
    if (phalf == 0) ss[pi] = ssum;
    __syncthreads();       // all attn MMAs done + ss visible; buffers reusable

    // fo = elu(acc/sum + bias) written to out in fragment layout (float2)
    {
        const size_t ob = (size_t)grow0 * 768 + c0g;
#pragma unroll
        for (int ma = 0; ma < 2; ++ma)
#pragma unroll
            for (int na = 0; na < 6; ++na) {
                int rb = wm * 32 + ma * 16 + g;
                int cb = wn * 48 + na * 8 + 2 * tig;
                float iv0 = 1.f / ss[rb];
                float iv1 = 1.f / ss[rb + 8];
                float b0 = __ldg(&bias[cb]), b1 = __ldg(&bias[cb + 1]);
                float v0 = fmaf(acc[ma][na][0], iv0, b0);
                float v1 = fmaf(acc[ma][na][1], iv0, b1);
                float v2 = fmaf(acc[ma][na][2], iv1, b0);
                float v3 = fmaf(acc[ma][na][3], iv1, b1);
                v0 = v0 > 0.f ? v0 : expm1f(v0);
                v1 = v1 > 0.f ? v1 : expm1f(v1);
                v2 = v2 > 0.f ? v2 : expm1f(v2);
                v3 = v3 > 0.f ? v3 : expm1f(v3);
                *(float2*)&out[ob + (size_t)rb * 768 + cb]       = make_float2(v0, v1);
                *(float2*)&out[ob + (size_t)(rb + 8) * 768 + cb] = make_float2(v2, v3);
            }
    }
    __threadfence_block();   // fo visible block-wide before gate epilogue reads

    // ---- Phase B: gate GEMM feat_in @ Hw^T for the same tile ----
#pragma unroll
    for (int ma = 0; ma < 2; ++ma)
#pragma unroll
        for (int na = 0; na < 6; ++na)
#pragma unroll
            for (int q = 0; q < 4; ++q) acc[ma][na][q] = 0.f;

    const uint4* __restrict__ Ah4 = (const uint4*)g_Ah;
    const uint4* __restrict__ Al4 = (const uint4*)g_Al;
    const uint4* __restrict__ Gh4 = (const uint4*)g_Hwh;
    const uint4* __restrict__ Gl4 = (const uint4*)g_Hwl;

    auto fill_g = [&](uint32_t bb, int k4) {
#pragma unroll
        for (int it = 0; it < 2; ++it) {
            int r = hr + it * 64;
            cp16(bb + O_AH + r * 80 + hc * 16, &Ah4[(grow0 + r) * 96 + k4 + hc]);
            cp16(bb + O_AL + r * 80 + hc * 16, &Al4[(grow0 + r) * 96 + k4 + hc]);
        }
        cp16(bb + O_WH + hr * 80 + hc * 16, &Gh4[(c0g + hr) * 96 + k4 + hc]);
        cp16(bb + O_WL + hr * 80 + hc * 16, &Gl4[(c0g + hr) * 96 + k4 + hc]);
        if (tid < 128) {
            cp16(bb + O_WH + (hr + 64) * 80 + hc * 16, &Gh4[(c0g + hr + 64) * 96 + k4 + hc]);
            cp16(bb + O_WL + (hr + 64) * 80 + hc * 16, &Gl4[(c0g + hr + 64) * 96 + k4 + hc]);
        }
        CP_COMMIT();
    };

    fill_g(sb, 0);
    fill_g(sb + BUF_STRIDE, 4);

    for (int ch = 0; ch < 24; ++ch) {
        if (ch < 22) CP_WAIT1(); else CP_WAIT0();
        __syncthreads();
        if (ch < 22) fill_g(sb + ((ch + 2) % 3) * BUF_STRIDE, (ch + 2) * 4);
        mma_chunk(sb + (ch % 3) * BUF_STRIDE, acc, wm, wn, a_off, b_off);
    }
    __syncthreads();

    // ---- Phase C: stage gate result, sigmoid blend in-place ----
    float* dtile = (float*)ds;   // overlays buffers (all consumed)
#pragma unroll
    for (int ma = 0; ma < 2; ++ma)
#pragma unroll
        for (int na = 0; na < 6; ++na) {
            int rb = wm * 32 + ma * 16 + g;
            int cb = wn * 48 + na * 8 + 2 * tig;
            dtile[rb * 97 + cb]           = acc[ma][na][0];
            dtile[rb * 97 + cb + 1]       = acc[ma][na][1];
            dtile[(rb + 8) * 97 + cb]     = acc[ma][na][2];
            dtile[(rb + 8) * 97 + cb + 1] = acc[ma][na][3];
        }
    __syncthreads();

    for (int i = tid; i < 128 * 96; i += 256) {
        int r = i / 96, c = i - r * 96;
        int row = grow0 + r, col = c0g + c;
        float v = dtile[r * 97 + c];
        float gg = 1.f / (1.f + __expf(-(v + __ldg(&Hb[col]))));
        size_t idx = (size_t)row * 768 + col;
        float fo = out[idx];            // written in Phase A by this block
        float xi = X[idx];
        out[idx] = fmaf(gg, fo - xi, xi);
    }
}

// ---------------------------------------------------------------------------
// Inputs (metadata order): feat_in, adj, W, b, w_src, w_dst, Hw, Hb
// ---------------------------------------------------------------------------
extern "C" void kernel_launch(void* const* d_in, const int* in_sizes, int n_in,
                              void* d_out, int out_size)
{
    const float* feat_in = (const float*)d_in[0];
    const float* adj     = (const float*)d_in[1];
    const float* W       = (const float*)d_in[2];
    const float* bias    = (const float*)d_in[3];
    const float* wsrc    = (const float*)d_in[4];
    const float* wdst    = (const float*)d_in[5];
    const float* Hw      = (const float*)d_in[6];
    const float* Hb      = (const float*)d_in[7];
    float* out           = (float*)d_out;
    (void)in_sizes; (void)n_in; (void)out_size;

    static bool attr_done = false;
    if (!attr_done) {
        cudaFuncSetAttribute(k_proj_mma, cudaFuncAttributeMaxDynamicSharedMemorySize, SM3_TOT);
        cudaFuncSetAttribute(k_attn_gate, cudaFuncAttributeMaxDynamicSharedMemorySize, SM2_TOT);
        attr_done = true;
    }

    k_prep_a<<<(8192 * 768 + 255) / 256, 256>>>(feat_in, Hw);
    k_prep_w<<<(8 * 96 * 768 + 255) / 256, 256>>>(W);
    k_prep_mask<<<(8 * 1024 * 1024) / 256, 256>>>(adj);
    k_proj_mma<<<dim3(64, 8), 256, SM3_TOT>>>(wsrc, wdst);
    k_attn_gate<<<dim3(64, 8), 256, SM2_TOT>>>(feat_in, bias, Hb, out);
}